// round 6
// baseline (speedup 1.0000x reference)
#include <cuda_runtime.h>
#include <cstdint>
#include <math.h>

#define NT 8192
#define DD 1024
#define FF 4096
#define NE 8
#define BM 128
#define BK 32
#define BN1 64
#define BN2 128
#define MAX_ROWS (NT*2 + NE*BM)   // 17408
#define MT (MAX_ROWS/BM)          // 136
#define GROUP 16
#define MTP (((MT+GROUP-1)/GROUP)*GROUP)   // 144

#define SA_STRIDE 36
#define STA (BM*SA_STRIDE)                 // 4608 floats
#define STB1 (2*BN1*SA_STRIDE)             // 4608 floats (2 mats x 64 rows)
#define STB2 (BN2*SA_STRIDE)               // 4608 floats
#define SMEM_BYTES ((2*STA + 2*STB1) * 4)  // 73728 (same for both ffn kernels)

// device-global scratch (allocation-free)
__device__ float g_h[(size_t)MAX_ROWS * FF];      // tf32 bits, K-permuted cols
__device__ float g_xg[(size_t)MAX_ROWS * DD];     // gathered x, tf32 bits, K-permuted
__device__ float g_w1t[(size_t)NE * FF * DD];     // [E][F][D'] tf32, K-permuted
__device__ float g_w3t[(size_t)NE * FF * DD];
__device__ float g_w2t[(size_t)NE * DD * FF];     // [E][D][F'] tf32, K-permuted
__device__ int   g_perm[MAX_ROWS];
__device__ float g_wt[MAX_ROWS];
__device__ int   g_counts[NE];
__device__ int   g_offs[NE + 1];
__device__ int   g_cursor[NE];
__device__ int   g_eid[NT * 2];
__device__ float g_wr[NT * 2];

__device__ __forceinline__ uint32_t f2tf(float f) {
    uint32_t u; asm("cvt.rna.tf32.f32 %0, %1;" : "=r"(u) : "f"(f)); return u;
}
__device__ __forceinline__ void mma_tf32(float c[4], const uint32_t a[4], const uint32_t b[2]) {
    asm volatile(
        "mma.sync.aligned.m16n8k8.row.col.f32.tf32.tf32.f32 "
        "{%0,%1,%2,%3}, {%4,%5,%6,%7}, {%8,%9}, {%0,%1,%2,%3};\n"
        : "+f"(c[0]), "+f"(c[1]), "+f"(c[2]), "+f"(c[3])
        : "r"(a[0]), "r"(a[1]), "r"(a[2]), "r"(a[3]), "r"(b[0]), "r"(b[1]));
}
__device__ __forceinline__ void cp16(uint32_t dst, const void* src) {
    asm volatile("cp.async.cg.shared.global [%0], [%1], 16;\n" :: "r"(dst), "l"(src));
}
#define CP_COMMIT() asm volatile("cp.async.commit_group;\n")

// k-permutation within a 32-block: k' = (k%4)*8 + k/4   (inverse: k = (j%8)*4 + j/8)
__device__ __forceinline__ int kperm(int inner) { return ((inner & 3) << 3) | (inner >> 2); }

// ---------------------------------------------------------------------------
__global__ void init_kernel(float* __restrict__ out) {
    int idx = blockIdx.x * blockDim.x + threadIdx.x;
    int stride = gridDim.x * blockDim.x;
    for (int i = idx; i < NT * DD; i += stride) out[i] = 0.f;
    for (int i = idx; i < MAX_ROWS; i += stride) g_perm[i] = -1;
    if (idx < NE) g_counts[idx] = 0;
}

__global__ void router_kernel(const float* __restrict__ x, const float* __restrict__ gw) {
    int warp = (blockIdx.x * blockDim.x + threadIdx.x) >> 5;
    int lane = threadIdx.x & 31;
    if (warp >= NT) return;
    const float* xr = x + (size_t)warp * DD;
    float acc[NE];
#pragma unroll
    for (int e = 0; e < NE; e++) acc[e] = 0.f;
    for (int d = lane; d < DD; d += 32) {
        float xv = xr[d];
        const float* g = gw + d * NE;
#pragma unroll
        for (int e = 0; e < NE; e++) acc[e] += xv * g[e];
    }
#pragma unroll
    for (int e = 0; e < NE; e++)
#pragma unroll
        for (int o = 16; o > 0; o >>= 1)
            acc[e] += __shfl_xor_sync(0xFFFFFFFFu, acc[e], o);
    if (lane == 0) {
        int i0 = 0; float v0 = acc[0];
#pragma unroll
        for (int e = 1; e < NE; e++) if (acc[e] > v0) { v0 = acc[e]; i0 = e; }
        int i1 = -1; float v1 = -1e30f;
#pragma unroll
        for (int e = 0; e < NE; e++) {
            if (e == i0) continue;
            if (acc[e] > v1) { v1 = acc[e]; i1 = e; }
        }
        float e1 = expf(v1 - v0);
        float inv = 1.f / (1.f + e1);
        g_eid[2 * warp + 0] = i0; g_wr[2 * warp + 0] = inv;
        g_eid[2 * warp + 1] = i1; g_wr[2 * warp + 1] = e1 * inv;
        atomicAdd(&g_counts[i0], 1);
        atomicAdd(&g_counts[i1], 1);
    }
}

__global__ void offsets_kernel() {
    int acc = 0;
    for (int e = 0; e < NE; e++) {
        g_offs[e] = acc; g_cursor[e] = acc;
        acc += (g_counts[e] + BM - 1) / BM * BM;
    }
    g_offs[NE] = acc;
}

__global__ void scatter_kernel() {
    int t = blockIdx.x * blockDim.x + threadIdx.x;
    if (t >= NT) return;
#pragma unroll
    for (int k = 0; k < 2; k++) {
        int e = g_eid[2 * t + k];
        int pos = atomicAdd(&g_cursor[e], 1);
        g_perm[pos] = t;
        g_wt[pos] = g_wr[2 * t + k];
    }
}

// Gather routed rows, tf32-round, K-permute. One float4 of output per thread-iter.
__global__ void gather_round_kernel(const float* __restrict__ x) {
    const int NC = DD / 4;
    int idx = blockIdx.x * blockDim.x + threadIdx.x;
    int stride = gridDim.x * blockDim.x;
    for (int i = idx; i < MAX_ROWS * NC; i += stride) {
        int r = i / NC, c4 = i % NC;
        int blk = c4 >> 3, o = c4 & 7;           // 32-float block, float4 within
        int p = g_perm[r];
        float4 v;
        if (p >= 0) {
            const float* xb = x + (size_t)p * DD + blk * 32;
            float t0[4];
#pragma unroll
            for (int m = 0; m < 4; m++) {
                int j = o * 4 + m;
                t0[m] = xb[((j & 7) << 2) | (j >> 3)];
            }
            v.x = __uint_as_float(f2tf(t0[0])); v.y = __uint_as_float(f2tf(t0[1]));
            v.z = __uint_as_float(f2tf(t0[2])); v.w = __uint_as_float(f2tf(t0[3]));
        } else v = make_float4(0.f, 0.f, 0.f, 0.f);
        reinterpret_cast<float4*>(g_xg)[(size_t)r * NC + c4] = v;
    }
}

// Transpose + tf32-round + K-permute weights. grid=(4096, 24): y = mat*8+expert.
__global__ void transpose_round_kernel(const float* __restrict__ w1,
                                       const float* __restrict__ w3,
                                       const float* __restrict__ w2) {
    __shared__ float s[32][33];
    int z = blockIdx.y, m = z >> 3, e = z & 7;
    const float* src; float* dst; int R, C;
    if (m == 0)      { src = w1 + (size_t)e * DD * FF; dst = g_w1t + (size_t)e * FF * DD; R = DD; C = FF; }
    else if (m == 1) { src = w3 + (size_t)e * DD * FF; dst = g_w3t + (size_t)e * FF * DD; R = DD; C = FF; }
    else             { src = w2 + (size_t)e * FF * DD; dst = g_w2t + (size_t)e * DD * FF; R = FF; C = DD; }
    int tpc = C / 32;
    int r0 = (blockIdx.x / tpc) * 32, c0 = (blockIdx.x % tpc) * 32;
    int rr = threadIdx.x >> 5, cc = threadIdx.x & 31;
#pragma unroll
    for (int i = 0; i < 4; i++)
        s[rr + 8 * i][cc] = src[(size_t)(r0 + rr + 8 * i) * C + c0 + cc];
    __syncthreads();
    int pcc = kperm(cc);
#pragma unroll
    for (int i = 0; i < 4; i++)
        dst[(size_t)(c0 + rr + 8 * i) * R + r0 + pcc] =
            __uint_as_float(f2tf(s[cc][rr + 8 * i]));
}

// ---------------------------------------------------------------------------
// FFN1: 128x64 tile, W1+W3 share A. All operands tf32 bits, K-permuted; pure
// LDS.128 + HMMA inner loop.
__global__ __launch_bounds__(256, 2) void ffn1_kernel() {
    extern __shared__ float smem[];
    float* sA = smem;                // [2][BM][36]
    float* sB = smem + 2 * STA;      // [2][2 mats][BN1][36]

    const int NBT = FF / BN1;  // 64
    int bid = blockIdx.x;
    int tm = (bid / (GROUP * NBT)) * GROUP + (bid % GROUP);
    int nb = (bid % (GROUP * NBT)) / GROUP;
    if (tm >= MT) return;
    const int r0 = tm * BM;
    if (r0 >= g_offs[NE]) return;
    const int n0 = nb * BN1;

    int e = NE - 1;
#pragma unroll
    for (int i = 0; i < NE; i++)
        if (r0 >= g_offs[i] && r0 < g_offs[i + 1]) e = i;
    const float* W1 = g_w1t + (size_t)e * FF * DD;
    const float* W3 = g_w3t + (size_t)e * FF * DD;

    const int tid = threadIdx.x;
    const int lane = tid & 31, warp = tid >> 5;
    const int wm = (warp >> 1) * 32, wn = (warp & 1) * 32;
    const int grp = lane >> 2, qid = lane & 3;

    uint32_t sA_u = (uint32_t)__cvta_generic_to_shared(sA);
    uint32_t sB_u = (uint32_t)__cvta_generic_to_shared(sB);

    float acc1[2][4][4], acc3[2][4][4];
#pragma unroll
    for (int mi = 0; mi < 2; mi++)
#pragma unroll
        for (int ni = 0; ni < 4; ni++)
#pragma unroll
            for (int t = 0; t < 4; t++) { acc1[mi][ni][t] = 0.f; acc3[mi][ni][t] = 0.f; }

    const int NK = DD / BK;  // 32
    const int arow = tid >> 3, ac16 = (tid & 7) * 4;

    auto load_stage = [&](int st, int k0) {
#pragma unroll
        for (int i = 0; i < 4; i++) {
            int row = arow + 32 * i;
            cp16(sA_u + (st * STA + row * SA_STRIDE + ac16) * 4,
                 g_xg + (size_t)(r0 + row) * DD + k0 + ac16);
        }
#pragma unroll
        for (int i = 0; i < 4; i++) {
            int idx = tid + i * 256;
            int mat = idx >> 9, row = (idx >> 3) & 63, c16 = (idx & 7) * 4;
            const float* W = mat ? W3 : W1;
            cp16(sB_u + (st * STB1 + (mat * BN1 + row) * SA_STRIDE + c16) * 4,
                 W + (size_t)(n0 + row) * DD + k0 + c16);
        }
        CP_COMMIT();
    };

    load_stage(0, 0);

    for (int k = 0; k < NK; k++) {
        int st = k & 1;
        if (k + 1 < NK) {
            load_stage(st ^ 1, (k + 1) * BK);
            asm volatile("cp.async.wait_group 1;\n");
        } else {
            asm volatile("cp.async.wait_group 0;\n");
        }
        __syncthreads();

        const float* A = sA + st * STA;
        const float* B = sB + st * STB1;
#pragma unroll
        for (int h = 0; h < 2; h++) {          // halves: slices {16h, 16h+8}
            float4 va[4];
#pragma unroll
            for (int j = 0; j < 4; j++)
                va[j] = *reinterpret_cast<const float4*>(
                    A + (wm + grp + 8 * j) * SA_STRIDE + qid * 8 + h * 4);
#pragma unroll
            for (int mat = 0; mat < 2; mat++) {
                float4 vb[4];
#pragma unroll
                for (int ni = 0; ni < 4; ni++)
                    vb[ni] = *reinterpret_cast<const float4*>(
                        B + (mat * BN1 + wn + ni * 8 + grp) * SA_STRIDE + qid * 8 + h * 4);
#pragma unroll
                for (int s = 0; s < 2; s++) {
                    uint32_t a[2][4];
#pragma unroll
                    for (int mi = 0; mi < 2; mi++) {
                        const float4& lo = va[2 * mi];
                        const float4& hi = va[2 * mi + 1];
                        a[mi][0] = __float_as_uint(s ? lo.z : lo.x);
                        a[mi][1] = __float_as_uint(s ? hi.z : hi.x);
                        a[mi][2] = __float_as_uint(s ? lo.w : lo.y);
                        a[mi][3] = __float_as_uint(s ? hi.w : hi.y);
                    }
#pragma unroll
                    for (int ni = 0; ni < 4; ni++) {
                        uint32_t b[2];
                        b[0] = __float_as_uint(s ? vb[ni].z : vb[ni].x);
                        b[1] = __float_as_uint(s ? vb[ni].w : vb[ni].y);
#pragma unroll
                        for (int mi = 0; mi < 2; mi++)
                            mma_tf32(mat ? acc3[mi][ni] : acc1[mi][ni], a[mi], b);
                    }
                }
            }
        }
        __syncthreads();
    }

    // Epilogue: SwiGLU -> g_h (tf32 bits, K-permuted columns)
#pragma unroll
    for (int mi = 0; mi < 2; mi++)
#pragma unroll
        for (int ni = 0; ni < 4; ni++)
#pragma unroll
            for (int t = 0; t < 4; t++) {
                int row = r0 + wm + mi * 16 + grp + ((t >= 2) ? 8 : 0);
                int c = wn + ni * 8 + qid * 2 + (t & 1);         // 0..63
                int cp = (c & ~31) | kperm(c & 31);
                float a = acc1[mi][ni][t];
                float s = a / (1.f + expf(-a));
                g_h[(size_t)row * FF + n0 + cp] =
                    __uint_as_float(f2tf(s * acc3[mi][ni][t]));
            }
}

// ---------------------------------------------------------------------------
// FFN2: 128x128 tile, A = g_h (pre-rounded, permuted), B = g_w2t.
__global__ __launch_bounds__(256, 2) void ffn2_kernel(float* __restrict__ out) {
    extern __shared__ float smem[];
    float* sA = smem;                // [2][BM][36]
    float* sB = smem + 2 * STA;      // [2][BN2][36]

    const int NBT = DD / BN2;  // 8
    int bid = blockIdx.x;
    int tm = (bid / (GROUP * NBT)) * GROUP + (bid % GROUP);
    int nb = (bid % (GROUP * NBT)) / GROUP;
    if (tm >= MT) return;
    const int r0 = tm * BM;
    if (r0 >= g_offs[NE]) return;
    const int n0 = nb * BN2;

    int e = NE - 1;
#pragma unroll
    for (int i = 0; i < NE; i++)
        if (r0 >= g_offs[i] && r0 < g_offs[i + 1]) e = i;
    const float* W2 = g_w2t + (size_t)e * DD * FF;

    const int tid = threadIdx.x;
    const int lane = tid & 31, warp = tid >> 5;
    const int wm = (warp >> 1) * 32, wn = (warp & 1) * 64;
    const int grp = lane >> 2, qid = lane & 3;

    uint32_t sA_u = (uint32_t)__cvta_generic_to_shared(sA);
    uint32_t sB_u = (uint32_t)__cvta_generic_to_shared(sB);

    float acc[2][8][4];
#pragma unroll
    for (int mi = 0; mi < 2; mi++)
#pragma unroll
        for (int ni = 0; ni < 8; ni++)
#pragma unroll
            for (int t = 0; t < 4; t++) acc[mi][ni][t] = 0.f;

    const int NK = FF / BK;  // 128
    const int arow = tid >> 3, ac16 = (tid & 7) * 4;

    auto load_stage = [&](int st, int k0) {
#pragma unroll
        for (int i = 0; i < 4; i++) {
            int row = arow + 32 * i;
            cp16(sA_u + (st * STA + row * SA_STRIDE + ac16) * 4,
                 g_h + (size_t)(r0 + row) * FF + k0 + ac16);
        }
#pragma unroll
        for (int i = 0; i < 4; i++) {
            int idx = tid + i * 256;
            int row = idx >> 3, c16 = (idx & 7) * 4;    // 128 rows x 8 chunks
            cp16(sB_u + (st * STB2 + row * SA_STRIDE + c16) * 4,
                 W2 + (size_t)(n0 + row) * FF + k0 + c16);
        }
        CP_COMMIT();
    };

    load_stage(0, 0);

    for (int k = 0; k < NK; k++) {
        int st = k & 1;
        if (k + 1 < NK) {
            load_stage(st ^ 1, (k + 1) * BK);
            asm volatile("cp.async.wait_group 1;\n");
        } else {
            asm volatile("cp.async.wait_group 0;\n");
        }
        __syncthreads();

        const float* A = sA + st * STA;
        const float* B = sB + st * STB2;
#pragma unroll
        for (int h = 0; h < 2; h++) {
            float4 va[4];
#pragma unroll
            for (int j = 0; j < 4; j++)
                va[j] = *reinterpret_cast<const float4*>(
                    A + (wm + grp + 8 * j) * SA_STRIDE + qid * 8 + h * 4);
#pragma unroll
            for (int nh = 0; nh < 2; nh++) {    // split 8 cols into 2x4 to cap regs
                float4 vb[4];
#pragma unroll
                for (int ni = 0; ni < 4; ni++)
                    vb[ni] = *reinterpret_cast<const float4*>(
                        B + (wn + (nh * 4 + ni) * 8 + grp) * SA_STRIDE + qid * 8 + h * 4);
#pragma unroll
                for (int s = 0; s < 2; s++) {
                    uint32_t a[2][4];
#pragma unroll
                    for (int mi = 0; mi < 2; mi++) {
                        const float4& lo = va[2 * mi];
                        const float4& hi = va[2 * mi + 1];
                        a[mi][0] = __float_as_uint(s ? lo.z : lo.x);
                        a[mi][1] = __float_as_uint(s ? hi.z : hi.x);
                        a[mi][2] = __float_as_uint(s ? lo.w : lo.y);
                        a[mi][3] = __float_as_uint(s ? hi.w : hi.y);
                    }
#pragma unroll
                    for (int ni = 0; ni < 4; ni++) {
                        uint32_t b[2];
                        b[0] = __float_as_uint(s ? vb[ni].z : vb[ni].x);
                        b[1] = __float_as_uint(s ? vb[ni].w : vb[ni].y);
#pragma unroll
                        for (int mi = 0; mi < 2; mi++)
                            mma_tf32(acc[mi][nh * 4 + ni], a[mi], b);
                    }
                }
            }
        }
        __syncthreads();
    }

#pragma unroll
    for (int mi = 0; mi < 2; mi++) {
#pragma unroll
        for (int t2 = 0; t2 < 2; t2++) {
            int row = r0 + wm + mi * 16 + grp + t2 * 8;
            int p = g_perm[row];
            if (p < 0) continue;
            float w = g_wt[row];
#pragma unroll
            for (int ni = 0; ni < 8; ni++) {
#pragma unroll
                for (int t = 0; t < 2; t++) {
                    int col = n0 + wn + ni * 8 + qid * 2 + t;
                    atomicAdd(out + (size_t)p * DD + col, acc[mi][ni][t2 * 2 + t] * w);
                }
            }
        }
    }
}

// ---------------------------------------------------------------------------
extern "C" void kernel_launch(void* const* d_in, const int* in_sizes, int n_in,
                              void* d_out, int out_size) {
    const float* x  = (const float*)d_in[0];
    const float* gw = (const float*)d_in[1];
    const float* w1 = (const float*)d_in[2];
    const float* w3 = (const float*)d_in[3];
    const float* w2 = (const float*)d_in[4];
    float* out = (float*)d_out;

    cudaFuncSetAttribute(ffn1_kernel, cudaFuncAttributeMaxDynamicSharedMemorySize, SMEM_BYTES);
    cudaFuncSetAttribute(ffn2_kernel, cudaFuncAttributeMaxDynamicSharedMemorySize, SMEM_BYTES);

    init_kernel<<<4096, 256>>>(out);
    router_kernel<<<NT / 8, 256>>>(x, gw);
    offsets_kernel<<<1, 1>>>();
    scatter_kernel<<<(NT + 255) / 256, 256>>>();
    gather_round_kernel<<<4096, 256>>>(x);
    transpose_round_kernel<<<dim3(4096, 24), 256>>>(w1, w3, w2);
    ffn1_kernel<<<MTP * (FF / BN1), 256, SMEM_BYTES>>>();
    ffn2_kernel<<<MTP * (DD / BN2), 256, SMEM_BYTES>>>(out);
}

// round 7
// speedup vs baseline: 2.2239x; 2.2239x over previous
#include <cuda_runtime.h>
#include <cuda_fp16.h>
#include <cstdint>
#include <math.h>

#define NT 8192
#define DD 1024
#define FF 4096
#define NE 8
#define BM 128
#define BK 64
#define BN1 64
#define BN2 128
#define MAX_ROWS (NT*2 + NE*BM)   // 17408
#define MT (MAX_ROWS/BM)          // 136
#define GROUP 16
#define MTP (((MT+GROUP-1)/GROUP)*GROUP)   // 144

#define PITCH 72                     // halves per smem row (144B = 9x16B)
#define STA_H (BM*PITCH)             // 9216 halves per A stage
#define STB_H (128*PITCH)            // 9216 halves per B stage (128 rows both kernels)
#define SMEM_BYTES ((2*STA_H + 2*STB_H) * 2)   // 73728

// device-global scratch (allocation-free)
__device__ __align__(128) __half g_h[(size_t)MAX_ROWS * FF];
__device__ __align__(128) __half g_xh[(size_t)MAX_ROWS * DD];
__device__ __align__(128) __half g_w1t[(size_t)NE * FF * DD];   // [E][F][D] K-major
__device__ __align__(128) __half g_w3t[(size_t)NE * FF * DD];
__device__ __align__(128) __half g_w2t[(size_t)NE * DD * FF];   // [E][D][F] K-major
__device__ int   g_perm[MAX_ROWS];
__device__ float g_wt[MAX_ROWS];
__device__ int   g_counts[NE];
__device__ int   g_offs[NE + 1];
__device__ int   g_cursor[NE];
__device__ int   g_eid[NT * 2];
__device__ float g_wr[NT * 2];

__device__ __forceinline__ void mma_f16(float c[4], const uint32_t a[4], const uint32_t b[2]) {
    asm volatile(
        "mma.sync.aligned.m16n8k16.row.col.f32.f16.f16.f32 "
        "{%0,%1,%2,%3}, {%4,%5,%6,%7}, {%8,%9}, {%0,%1,%2,%3};\n"
        : "+f"(c[0]), "+f"(c[1]), "+f"(c[2]), "+f"(c[3])
        : "r"(a[0]), "r"(a[1]), "r"(a[2]), "r"(a[3]), "r"(b[0]), "r"(b[1]));
}
__device__ __forceinline__ void cp16(uint32_t dst, const void* src) {
    asm volatile("cp.async.cg.shared.global [%0], [%1], 16;\n" :: "r"(dst), "l"(src));
}
#define CP_COMMIT() asm volatile("cp.async.commit_group;\n")

// ---------------------------------------------------------------------------
__global__ void init_kernel(float* __restrict__ out) {
    int idx = blockIdx.x * blockDim.x + threadIdx.x;
    int stride = gridDim.x * blockDim.x;
    for (int i = idx; i < NT * DD; i += stride) out[i] = 0.f;
    for (int i = idx; i < MAX_ROWS; i += stride) g_perm[i] = -1;
    if (idx < NE) g_counts[idx] = 0;
}

__global__ void router_kernel(const float* __restrict__ x, const float* __restrict__ gw) {
    int warp = (blockIdx.x * blockDim.x + threadIdx.x) >> 5;
    int lane = threadIdx.x & 31;
    if (warp >= NT) return;
    const float* xr = x + (size_t)warp * DD;
    float acc[NE];
#pragma unroll
    for (int e = 0; e < NE; e++) acc[e] = 0.f;
    for (int d = lane; d < DD; d += 32) {
        float xv = xr[d];
        const float* g = gw + d * NE;
#pragma unroll
        for (int e = 0; e < NE; e++) acc[e] += xv * g[e];
    }
#pragma unroll
    for (int e = 0; e < NE; e++)
#pragma unroll
        for (int o = 16; o > 0; o >>= 1)
            acc[e] += __shfl_xor_sync(0xFFFFFFFFu, acc[e], o);
    if (lane == 0) {
        int i0 = 0; float v0 = acc[0];
#pragma unroll
        for (int e = 1; e < NE; e++) if (acc[e] > v0) { v0 = acc[e]; i0 = e; }
        int i1 = -1; float v1 = -1e30f;
#pragma unroll
        for (int e = 0; e < NE; e++) {
            if (e == i0) continue;
            if (acc[e] > v1) { v1 = acc[e]; i1 = e; }
        }
        float e1 = expf(v1 - v0);
        float inv = 1.f / (1.f + e1);
        g_eid[2 * warp + 0] = i0; g_wr[2 * warp + 0] = inv;
        g_eid[2 * warp + 1] = i1; g_wr[2 * warp + 1] = e1 * inv;
        atomicAdd(&g_counts[i0], 1);
        atomicAdd(&g_counts[i1], 1);
    }
}

__global__ void offsets_kernel() {
    int acc = 0;
    for (int e = 0; e < NE; e++) {
        g_offs[e] = acc; g_cursor[e] = acc;
        acc += (g_counts[e] + BM - 1) / BM * BM;
    }
    g_offs[NE] = acc;
}

__global__ void scatter_kernel() {
    int t = blockIdx.x * blockDim.x + threadIdx.x;
    if (t >= NT) return;
#pragma unroll
    for (int k = 0; k < 2; k++) {
        int e = g_eid[2 * t + k];
        int pos = atomicAdd(&g_cursor[e], 1);
        g_perm[pos] = t;
        g_wt[pos] = g_wr[2 * t + k];
    }
}

// Gather routed rows -> fp16 (8 halves = 16B per thread-iter).
__global__ void gather_half_kernel(const float* __restrict__ x) {
    const int NC8 = DD / 8;
    int idx = blockIdx.x * blockDim.x + threadIdx.x;
    int stride = gridDim.x * blockDim.x;
    for (int i = idx; i < MAX_ROWS * NC8; i += stride) {
        int r = i / NC8, c8 = i % NC8;
        int p = g_perm[r];
        union { uint4 u; __half2 h[4]; } pk;
        if (p >= 0) {
            const float4* xs = reinterpret_cast<const float4*>(x + (size_t)p * DD + c8 * 8);
            float4 v0 = xs[0], v1 = xs[1];
            pk.h[0] = __floats2half2_rn(v0.x, v0.y);
            pk.h[1] = __floats2half2_rn(v0.z, v0.w);
            pk.h[2] = __floats2half2_rn(v1.x, v1.y);
            pk.h[3] = __floats2half2_rn(v1.z, v1.w);
        } else {
            pk.u = make_uint4(0, 0, 0, 0);
        }
        reinterpret_cast<uint4*>(g_xh)[(size_t)r * NC8 + c8] = pk.u;
    }
}

// Transpose weights to K-major fp16. grid=(4096, 24): y = mat*8+expert.
__global__ void transpose_half_kernel(const float* __restrict__ w1,
                                      const float* __restrict__ w3,
                                      const float* __restrict__ w2) {
    __shared__ float s[32][33];
    int z = blockIdx.y, m = z >> 3, e = z & 7;
    const float* src; __half* dst; int R, C;
    if (m == 0)      { src = w1 + (size_t)e * DD * FF; dst = g_w1t + (size_t)e * FF * DD; R = DD; C = FF; }
    else if (m == 1) { src = w3 + (size_t)e * DD * FF; dst = g_w3t + (size_t)e * FF * DD; R = DD; C = FF; }
    else             { src = w2 + (size_t)e * FF * DD; dst = g_w2t + (size_t)e * DD * FF; R = FF; C = DD; }
    int tpc = C / 32;
    int r0 = (blockIdx.x / tpc) * 32, c0 = (blockIdx.x % tpc) * 32;
    int rr = threadIdx.x >> 5, cc = threadIdx.x & 31;
#pragma unroll
    for (int i = 0; i < 4; i++)
        s[rr + 8 * i][cc] = src[(size_t)(r0 + rr + 8 * i) * C + c0 + cc];
    __syncthreads();
#pragma unroll
    for (int i = 0; i < 4; i++)
        dst[(size_t)(c0 + rr + 8 * i) * R + r0 + cc] = __float2half_rn(s[cc][rr + 8 * i]);
}

// ---------------------------------------------------------------------------
// FFN1: h = silu(X W1) * (X W3), fp16 operands, m16n8k16 HMMA, BK=64.
__global__ __launch_bounds__(256, 2) void ffn1_kernel() {
    extern __shared__ __half smem_h[];
    __half* sA = smem_h;                 // [2][BM][PITCH]
    __half* sB = smem_h + 2 * STA_H;     // [2][2 mats x 64][PITCH]

    const int NBT = FF / BN1;  // 64
    int bid = blockIdx.x;
    int tm = (bid / (GROUP * NBT)) * GROUP + (bid % GROUP);
    int nb = (bid % (GROUP * NBT)) / GROUP;
    if (tm >= MT) return;
    const int r0 = tm * BM;
    if (r0 >= g_offs[NE]) return;
    const int n0 = nb * BN1;

    int e = NE - 1;
#pragma unroll
    for (int i = 0; i < NE; i++)
        if (r0 >= g_offs[i] && r0 < g_offs[i + 1]) e = i;
    const __half* W1 = g_w1t + (size_t)e * FF * DD;
    const __half* W3 = g_w3t + (size_t)e * FF * DD;

    const int tid = threadIdx.x;
    const int lane = tid & 31, warp = tid >> 5;
    const int wm = (warp >> 1) * 32, wn = (warp & 1) * 32;
    const int grp = lane >> 2, qid = lane & 3;

    uint32_t sA_u = (uint32_t)__cvta_generic_to_shared(sA);
    uint32_t sB_u = (uint32_t)__cvta_generic_to_shared(sB);

    float acc1[2][4][4], acc3[2][4][4];
#pragma unroll
    for (int mi = 0; mi < 2; mi++)
#pragma unroll
        for (int ni = 0; ni < 4; ni++)
#pragma unroll
            for (int t = 0; t < 4; t++) { acc1[mi][ni][t] = 0.f; acc3[mi][ni][t] = 0.f; }

    const int NK = DD / BK;  // 16

    auto load_stage = [&](int st, int k0) {
#pragma unroll
        for (int i = 0; i < 4; i++) {
            int idx = tid + i * 256;
            int row = idx >> 3, c16 = (idx & 7) * 8;     // halves
            cp16(sA_u + (st * STA_H + row * PITCH + c16) * 2,
                 g_xh + (size_t)(r0 + row) * DD + k0 + c16);
        }
#pragma unroll
        for (int i = 0; i < 4; i++) {
            int idx = tid + i * 256;
            int mat = idx >> 9, row = (idx >> 3) & 63, c16 = (idx & 7) * 8;
            const __half* W = mat ? W3 : W1;
            cp16(sB_u + (st * STB_H + (mat * 64 + row) * PITCH + c16) * 2,
                 W + (size_t)(n0 + row) * DD + k0 + c16);
        }
        CP_COMMIT();
    };

    load_stage(0, 0);

    for (int k = 0; k < NK; k++) {
        int st = k & 1;
        if (k + 1 < NK) {
            load_stage(st ^ 1, (k + 1) * BK);
            asm volatile("cp.async.wait_group 1;\n");
        } else {
            asm volatile("cp.async.wait_group 0;\n");
        }
        __syncthreads();

        const __half* A = sA + st * STA_H;
        const __half* B = sB + st * STB_H;
#pragma unroll
        for (int c = 0; c < 4; c++) {
            int kc = c * 16 + qid * 2;
            uint32_t a[2][4];
#pragma unroll
            for (int mi = 0; mi < 2; mi++) {
                const __half* p0 = A + (wm + mi * 16 + grp) * PITCH + kc;
                a[mi][0] = *reinterpret_cast<const uint32_t*>(p0);
                a[mi][1] = *reinterpret_cast<const uint32_t*>(p0 + 8 * PITCH);
                a[mi][2] = *reinterpret_cast<const uint32_t*>(p0 + 8);
                a[mi][3] = *reinterpret_cast<const uint32_t*>(p0 + 8 * PITCH + 8);
            }
#pragma unroll
            for (int mat = 0; mat < 2; mat++) {
#pragma unroll
                for (int ni = 0; ni < 4; ni++) {
                    const __half* pb = B + ((mat << 6) + wn + ni * 8 + grp) * PITCH + kc;
                    uint32_t b[2];
                    b[0] = *reinterpret_cast<const uint32_t*>(pb);
                    b[1] = *reinterpret_cast<const uint32_t*>(pb + 8);
#pragma unroll
                    for (int mi = 0; mi < 2; mi++)
                        mma_f16(mat ? acc3[mi][ni] : acc1[mi][ni], a[mi], b);
                }
            }
        }
        __syncthreads();
    }

    // Epilogue: SwiGLU -> g_h (fp16, half2 stores)
#pragma unroll
    for (int mi = 0; mi < 2; mi++)
#pragma unroll
        for (int ni = 0; ni < 4; ni++)
#pragma unroll
            for (int t2 = 0; t2 < 2; t2++) {
                int row = r0 + wm + mi * 16 + grp + t2 * 8;
                int col = n0 + wn + ni * 8 + qid * 2;
                float a0 = acc1[mi][ni][t2 * 2 + 0], a1 = acc1[mi][ni][t2 * 2 + 1];
                float s0 = a0 / (1.f + expf(-a0)) * acc3[mi][ni][t2 * 2 + 0];
                float s1 = a1 / (1.f + expf(-a1)) * acc3[mi][ni][t2 * 2 + 1];
                *reinterpret_cast<__half2*>(g_h + (size_t)row * FF + col) =
                    __floats2half2_rn(s0, s1);
            }
}

// ---------------------------------------------------------------------------
// FFN2: out[token] += wt * (h @ W2), fp16 operands, BN=128, BK=64.
__global__ __launch_bounds__(256, 2) void ffn2_kernel(float* __restrict__ out) {
    extern __shared__ __half smem_h[];
    __half* sA = smem_h;                 // [2][BM][PITCH]
    __half* sB = smem_h + 2 * STA_H;     // [2][BN2][PITCH]

    const int NBT = DD / BN2;  // 8
    int bid = blockIdx.x;
    int tm = (bid / (GROUP * NBT)) * GROUP + (bid % GROUP);
    int nb = (bid % (GROUP * NBT)) / GROUP;
    if (tm >= MT) return;
    const int r0 = tm * BM;
    if (r0 >= g_offs[NE]) return;
    const int n0 = nb * BN2;

    int e = NE - 1;
#pragma unroll
    for (int i = 0; i < NE; i++)
        if (r0 >= g_offs[i] && r0 < g_offs[i + 1]) e = i;
    const __half* W2 = g_w2t + (size_t)e * DD * FF;

    const int tid = threadIdx.x;
    const int lane = tid & 31, warp = tid >> 5;
    const int wm = (warp >> 1) * 32, wn = (warp & 1) * 64;
    const int grp = lane >> 2, qid = lane & 3;

    uint32_t sA_u = (uint32_t)__cvta_generic_to_shared(sA);
    uint32_t sB_u = (uint32_t)__cvta_generic_to_shared(sB);

    float acc[2][8][4];
#pragma unroll
    for (int mi = 0; mi < 2; mi++)
#pragma unroll
        for (int ni = 0; ni < 8; ni++)
#pragma unroll
            for (int t = 0; t < 4; t++) acc[mi][ni][t] = 0.f;

    const int NK = FF / BK;  // 64

    auto load_stage = [&](int st, int k0) {
#pragma unroll
        for (int i = 0; i < 4; i++) {
            int idx = tid + i * 256;
            int row = idx >> 3, c16 = (idx & 7) * 8;
            cp16(sA_u + (st * STA_H + row * PITCH + c16) * 2,
                 g_h + (size_t)(r0 + row) * FF + k0 + c16);
        }
#pragma unroll
        for (int i = 0; i < 4; i++) {
            int idx = tid + i * 256;
            int row = idx >> 3, c16 = (idx & 7) * 8;
            cp16(sB_u + (st * STB_H + row * PITCH + c16) * 2,
                 W2 + (size_t)(n0 + row) * FF + k0 + c16);
        }
        CP_COMMIT();
    };

    load_stage(0, 0);

    for (int k = 0; k < NK; k++) {
        int st = k & 1;
        if (k + 1 < NK) {
            load_stage(st ^ 1, (k + 1) * BK);
            asm volatile("cp.async.wait_group 1;\n");
        } else {
            asm volatile("cp.async.wait_group 0;\n");
        }
        __syncthreads();

        const __half* A = sA + st * STA_H;
        const __half* B = sB + st * STB_H;
#pragma unroll
        for (int c = 0; c < 4; c++) {
            int kc = c * 16 + qid * 2;
            uint32_t a[2][4];
#pragma unroll
            for (int mi = 0; mi < 2; mi++) {
                const __half* p0 = A + (wm + mi * 16 + grp) * PITCH + kc;
                a[mi][0] = *reinterpret_cast<const uint32_t*>(p0);
                a[mi][1] = *reinterpret_cast<const uint32_t*>(p0 + 8 * PITCH);
                a[mi][2] = *reinterpret_cast<const uint32_t*>(p0 + 8);
                a[mi][3] = *reinterpret_cast<const uint32_t*>(p0 + 8 * PITCH + 8);
            }
#pragma unroll
            for (int ni = 0; ni < 8; ni++) {
                const __half* pb = B + (wn + ni * 8 + grp) * PITCH + kc;
                uint32_t b[2];
                b[0] = *reinterpret_cast<const uint32_t*>(pb);
                b[1] = *reinterpret_cast<const uint32_t*>(pb + 8);
#pragma unroll
                for (int mi = 0; mi < 2; mi++)
                    mma_f16(acc[mi][ni], a[mi], b);
            }
        }
        __syncthreads();
    }

#pragma unroll
    for (int mi = 0; mi < 2; mi++) {
#pragma unroll
        for (int t2 = 0; t2 < 2; t2++) {
            int row = r0 + wm + mi * 16 + grp + t2 * 8;
            int p = g_perm[row];
            if (p < 0) continue;
            float w = g_wt[row];
#pragma unroll
            for (int ni = 0; ni < 8; ni++) {
#pragma unroll
                for (int t = 0; t < 2; t++) {
                    int col = n0 + wn + ni * 8 + qid * 2 + t;
                    atomicAdd(out + (size_t)p * DD + col, acc[mi][ni][t2 * 2 + t] * w);
                }
            }
        }
    }
}

// ---------------------------------------------------------------------------
extern "C" void kernel_launch(void* const* d_in, const int* in_sizes, int n_in,
                              void* d_out, int out_size) {
    const float* x  = (const float*)d_in[0];
    const float* gw = (const float*)d_in[1];
    const float* w1 = (const float*)d_in[2];
    const float* w3 = (const float*)d_in[3];
    const float* w2 = (const float*)d_in[4];
    float* out = (float*)d_out;

    cudaFuncSetAttribute(ffn1_kernel, cudaFuncAttributeMaxDynamicSharedMemorySize, SMEM_BYTES);
    cudaFuncSetAttribute(ffn2_kernel, cudaFuncAttributeMaxDynamicSharedMemorySize, SMEM_BYTES);

    init_kernel<<<4096, 256>>>(out);
    router_kernel<<<NT / 8, 256>>>(x, gw);
    offsets_kernel<<<1, 1>>>();
    scatter_kernel<<<(NT + 255) / 256, 256>>>();
    gather_half_kernel<<<4096, 256>>>(x);
    transpose_half_kernel<<<dim3(4096, 24), 256>>>(w1, w3, w2);
    ffn1_kernel<<<MTP * (FF / BN1), 256, SMEM_BYTES>>>();
    ffn2_kernel<<<MTP * (DD / BN2), 256, SMEM_BYTES>>>(out);
}

// round 8
// speedup vs baseline: 2.3961x; 1.0774x over previous
#include <cuda_runtime.h>
#include <cuda_fp16.h>
#include <cstdint>
#include <math.h>

#define NT 8192
#define DD 1024
#define FF 4096
#define NE 8
#define BM 128
#define BK 64
#define BN1 64
#define BN2 128
#define MAX_ROWS (NT*2 + NE*BM)   // 17408
#define MT (MAX_ROWS/BM)          // 136
#define GROUP 16
#define MTP (((MT+GROUP-1)/GROUP)*GROUP)   // 144

#define PITCH 72                     // halves per smem row (144B)
#define STA_H (BM*PITCH)
#define STB_H (128*PITCH)
#define SMEM_BYTES ((2*STA_H + 2*STB_H) * 2)   // 73728

__device__ __align__(128) __half g_h[(size_t)MAX_ROWS * FF];
__device__ __align__(128) __half g_xh[(size_t)MAX_ROWS * DD];
__device__ __align__(128) __half g_w1t[(size_t)NE * FF * DD];
__device__ __align__(128) __half g_w3t[(size_t)NE * FF * DD];
__device__ __align__(128) __half g_w2t[(size_t)NE * DD * FF];
__device__ __align__(128) float  g_o[(size_t)MAX_ROWS * DD];   // per-assignment ffn2 out
__device__ int   g_perm[MAX_ROWS];
__device__ float g_wt[MAX_ROWS];
__device__ int   g_tpos[NT * 2];
__device__ int   g_counts[NE];
__device__ int   g_offs[NE + 1];
__device__ int   g_cursor[NE];
__device__ int   g_eid[NT * 2];
__device__ float g_wr[NT * 2];

__device__ __forceinline__ void mma_f16(float c[4], const uint32_t a[4], const uint32_t b0, const uint32_t b1) {
    asm volatile(
        "mma.sync.aligned.m16n8k16.row.col.f32.f16.f16.f32 "
        "{%0,%1,%2,%3}, {%4,%5,%6,%7}, {%8,%9}, {%0,%1,%2,%3};\n"
        : "+f"(c[0]), "+f"(c[1]), "+f"(c[2]), "+f"(c[3])
        : "r"(a[0]), "r"(a[1]), "r"(a[2]), "r"(a[3]), "r"(b0), "r"(b1));
}
__device__ __forceinline__ void ldsm4(uint32_t r[4], uint32_t addr) {
    asm volatile("ldmatrix.sync.aligned.m8n8.x4.shared.b16 {%0,%1,%2,%3}, [%4];"
                 : "=r"(r[0]), "=r"(r[1]), "=r"(r[2]), "=r"(r[3]) : "r"(addr));
}
__device__ __forceinline__ void cp16(uint32_t dst, const void* src) {
    asm volatile("cp.async.cg.shared.global [%0], [%1], 16;\n" :: "r"(dst), "l"(src));
}
#define CP_COMMIT() asm volatile("cp.async.commit_group;\n")

// ---------------------------------------------------------------------------
__global__ void init_kernel() {
    int idx = blockIdx.x * blockDim.x + threadIdx.x;
    int stride = gridDim.x * blockDim.x;
    for (int i = idx; i < MAX_ROWS; i += stride) g_perm[i] = -1;
    if (idx < NE) g_counts[idx] = 0;
}

__global__ void router_kernel(const float* __restrict__ x, const float* __restrict__ gw) {
    int warp = (blockIdx.x * blockDim.x + threadIdx.x) >> 5;
    int lane = threadIdx.x & 31;
    if (warp >= NT) return;
    const float* xr = x + (size_t)warp * DD;
    float acc[NE];
#pragma unroll
    for (int e = 0; e < NE; e++) acc[e] = 0.f;
    for (int d = lane; d < DD; d += 32) {
        float xv = xr[d];
        const float* g = gw + d * NE;
#pragma unroll
        for (int e = 0; e < NE; e++) acc[e] += xv * g[e];
    }
#pragma unroll
    for (int e = 0; e < NE; e++)
#pragma unroll
        for (int o = 16; o > 0; o >>= 1)
            acc[e] += __shfl_xor_sync(0xFFFFFFFFu, acc[e], o);
    if (lane == 0) {
        int i0 = 0; float v0 = acc[0];
#pragma unroll
        for (int e = 1; e < NE; e++) if (acc[e] > v0) { v0 = acc[e]; i0 = e; }
        int i1 = -1; float v1 = -1e30f;
#pragma unroll
        for (int e = 0; e < NE; e++) {
            if (e == i0) continue;
            if (acc[e] > v1) { v1 = acc[e]; i1 = e; }
        }
        float e1 = expf(v1 - v0);
        float inv = 1.f / (1.f + e1);
        g_eid[2 * warp + 0] = i0; g_wr[2 * warp + 0] = inv;
        g_eid[2 * warp + 1] = i1; g_wr[2 * warp + 1] = e1 * inv;
        atomicAdd(&g_counts[i0], 1);
        atomicAdd(&g_counts[i1], 1);
    }
}

__global__ void offsets_kernel() {
    int acc = 0;
    for (int e = 0; e < NE; e++) {
        g_offs[e] = acc; g_cursor[e] = acc;
        acc += (g_counts[e] + BM - 1) / BM * BM;
    }
    g_offs[NE] = acc;
}

__global__ void scatter_kernel() {
    int t = blockIdx.x * blockDim.x + threadIdx.x;
    if (t >= NT) return;
#pragma unroll
    for (int k = 0; k < 2; k++) {
        int e = g_eid[2 * t + k];
        int pos = atomicAdd(&g_cursor[e], 1);
        g_perm[pos] = t;
        g_wt[pos] = g_wr[2 * t + k];
        g_tpos[2 * t + k] = pos;
    }
}

__global__ void gather_half_kernel(const float* __restrict__ x) {
    const int NC8 = DD / 8;
    int idx = blockIdx.x * blockDim.x + threadIdx.x;
    int stride = gridDim.x * blockDim.x;
    for (int i = idx; i < MAX_ROWS * NC8; i += stride) {
        int r = i / NC8, c8 = i % NC8;
        int p = g_perm[r];
        union { uint4 u; __half2 h[4]; } pk;
        if (p >= 0) {
            const float4* xs = reinterpret_cast<const float4*>(x + (size_t)p * DD + c8 * 8);
            float4 v0 = xs[0], v1 = xs[1];
            pk.h[0] = __floats2half2_rn(v0.x, v0.y);
            pk.h[1] = __floats2half2_rn(v0.z, v0.w);
            pk.h[2] = __floats2half2_rn(v1.x, v1.y);
            pk.h[3] = __floats2half2_rn(v1.z, v1.w);
        } else {
            pk.u = make_uint4(0, 0, 0, 0);
        }
        reinterpret_cast<uint4*>(g_xh)[(size_t)r * NC8 + c8] = pk.u;
    }
}

__global__ void transpose_half_kernel(const float* __restrict__ w1,
                                      const float* __restrict__ w3,
                                      const float* __restrict__ w2) {
    __shared__ float s[32][33];
    int z = blockIdx.y, m = z >> 3, e = z & 7;
    const float* src; __half* dst; int R, C;
    if (m == 0)      { src = w1 + (size_t)e * DD * FF; dst = g_w1t + (size_t)e * FF * DD; R = DD; C = FF; }
    else if (m == 1) { src = w3 + (size_t)e * DD * FF; dst = g_w3t + (size_t)e * FF * DD; R = DD; C = FF; }
    else             { src = w2 + (size_t)e * FF * DD; dst = g_w2t + (size_t)e * DD * FF; R = FF; C = DD; }
    int tpc = C / 32;
    int r0 = (blockIdx.x / tpc) * 32, c0 = (blockIdx.x % tpc) * 32;
    int rr = threadIdx.x >> 5, cc = threadIdx.x & 31;
#pragma unroll
    for (int i = 0; i < 4; i++)
        s[rr + 8 * i][cc] = src[(size_t)(r0 + rr + 8 * i) * C + c0 + cc];
    __syncthreads();
#pragma unroll
    for (int i = 0; i < 4; i++)
        dst[(size_t)(c0 + rr + 8 * i) * R + r0 + cc] = __float2half_rn(s[cc][rr + 8 * i]);
}

// ---------------------------------------------------------------------------
// FFN1: h = silu(X W1) * (X W3). fp16 m16n8k16 HMMA, ldmatrix fragments.
__global__ __launch_bounds__(256, 2) void ffn1_kernel() {
    extern __shared__ __half smem_h[];
    __half* sA = smem_h;
    __half* sB = smem_h + 2 * STA_H;

    const int NBT = FF / BN1;  // 64
    int bid = blockIdx.x;
    int tm = (bid / (GROUP * NBT)) * GROUP + (bid % GROUP);
    int nb = (bid % (GROUP * NBT)) / GROUP;
    if (tm >= MT) return;
    const int r0 = tm * BM;
    if (r0 >= g_offs[NE]) return;
    const int n0 = nb * BN1;

    int e = NE - 1;
#pragma unroll
    for (int i = 0; i < NE; i++)
        if (r0 >= g_offs[i] && r0 < g_offs[i + 1]) e = i;
    const __half* W1 = g_w1t + (size_t)e * FF * DD;
    const __half* W3 = g_w3t + (size_t)e * FF * DD;

    const int tid = threadIdx.x;
    const int lane = tid & 31, warp = tid >> 5;
    const int wm = (warp >> 1) * 32, wn = (warp & 1) * 32;
    const int grp = lane >> 2, qid = lane & 3;

    // ldmatrix lane address components
    const int lrA = (lane & 7) + ((lane >> 3) & 1) * 8;   // m row within m16
    const int kgA = (lane >> 4) * 8;                       // k offset
    const int lrB = (lane & 7) + ((lane >> 4) & 1) * 8;   // n row within n16
    const int kgB = ((lane >> 3) & 1) * 8;

    uint32_t sA_u = (uint32_t)__cvta_generic_to_shared(sA);
    uint32_t sB_u = (uint32_t)__cvta_generic_to_shared(sB);

    float acc1[2][4][4], acc3[2][4][4];
#pragma unroll
    for (int mi = 0; mi < 2; mi++)
#pragma unroll
        for (int ni = 0; ni < 4; ni++)
#pragma unroll
            for (int t = 0; t < 4; t++) { acc1[mi][ni][t] = 0.f; acc3[mi][ni][t] = 0.f; }

    const int NK = DD / BK;  // 16

    auto load_stage = [&](int st, int k0) {
#pragma unroll
        for (int i = 0; i < 4; i++) {
            int idx = tid + i * 256;
            int row = idx >> 3, c16 = (idx & 7) * 8;
            cp16(sA_u + (st * STA_H + row * PITCH + c16) * 2,
                 g_xh + (size_t)(r0 + row) * DD + k0 + c16);
        }
#pragma unroll
        for (int i = 0; i < 4; i++) {
            int idx = tid + i * 256;
            int mat = idx >> 9, row = (idx >> 3) & 63, c16 = (idx & 7) * 8;
            const __half* W = mat ? W3 : W1;
            cp16(sB_u + (st * STB_H + (mat * 64 + row) * PITCH + c16) * 2,
                 W + (size_t)(n0 + row) * DD + k0 + c16);
        }
        CP_COMMIT();
    };

    load_stage(0, 0);

    for (int k = 0; k < NK; k++) {
        int st = k & 1;
        if (k + 1 < NK) {
            load_stage(st ^ 1, (k + 1) * BK);
            asm volatile("cp.async.wait_group 1;\n");
        } else {
            asm volatile("cp.async.wait_group 0;\n");
        }
        __syncthreads();

        uint32_t Au = sA_u + st * STA_H * 2;
        uint32_t Bu = sB_u + st * STB_H * 2;
#pragma unroll
        for (int c = 0; c < 4; c++) {
            int kc = c * 16;
            uint32_t a[2][4];
#pragma unroll
            for (int mi = 0; mi < 2; mi++)
                ldsm4(a[mi], Au + ((wm + mi * 16 + lrA) * PITCH + kc + kgA) * 2);
#pragma unroll
            for (int mat = 0; mat < 2; mat++) {
#pragma unroll
                for (int p = 0; p < 2; p++) {
                    uint32_t b[4];
                    ldsm4(b, Bu + ((mat * 64 + wn + p * 16 + lrB) * PITCH + kc + kgB) * 2);
#pragma unroll
                    for (int mi = 0; mi < 2; mi++) {
                        float* d0 = mat ? acc3[mi][p * 2 + 0] : acc1[mi][p * 2 + 0];
                        float* d1 = mat ? acc3[mi][p * 2 + 1] : acc1[mi][p * 2 + 1];
                        mma_f16(d0, a[mi], b[0], b[1]);
                        mma_f16(d1, a[mi], b[2], b[3]);
                    }
                }
            }
        }
        __syncthreads();
    }

    // Epilogue: SwiGLU -> g_h (fp16)
#pragma unroll
    for (int mi = 0; mi < 2; mi++)
#pragma unroll
        for (int ni = 0; ni < 4; ni++)
#pragma unroll
            for (int t2 = 0; t2 < 2; t2++) {
                int row = r0 + wm + mi * 16 + grp + t2 * 8;
                int col = n0 + wn + ni * 8 + qid * 2;
                float a0 = acc1[mi][ni][t2 * 2 + 0], a1 = acc1[mi][ni][t2 * 2 + 1];
                float s0 = a0 / (1.f + expf(-a0)) * acc3[mi][ni][t2 * 2 + 0];
                float s1 = a1 / (1.f + expf(-a1)) * acc3[mi][ni][t2 * 2 + 1];
                *reinterpret_cast<__half2*>(g_h + (size_t)row * FF + col) =
                    __floats2half2_rn(s0, s1);
            }
}

// ---------------------------------------------------------------------------
// FFN2: g_o[row] = h[row] @ W2  (no weights, no atomics).
__global__ __launch_bounds__(256, 2) void ffn2_kernel() {
    extern __shared__ __half smem_h[];
    __half* sA = smem_h;
    __half* sB = smem_h + 2 * STA_H;

    const int NBT = DD / BN2;  // 8
    int bid = blockIdx.x;
    int tm = (bid / (GROUP * NBT)) * GROUP + (bid % GROUP);
    int nb = (bid % (GROUP * NBT)) / GROUP;
    if (tm >= MT) return;
    const int r0 = tm * BM;
    if (r0 >= g_offs[NE]) return;
    const int n0 = nb * BN2;

    int e = NE - 1;
#pragma unroll
    for (int i = 0; i < NE; i++)
        if (r0 >= g_offs[i] && r0 < g_offs[i + 1]) e = i;
    const __half* W2 = g_w2t + (size_t)e * DD * FF;

    const int tid = threadIdx.x;
    const int lane = tid & 31, warp = tid >> 5;
    const int wm = (warp >> 1) * 32, wn = (warp & 1) * 64;
    const int grp = lane >> 2, qid = lane & 3;

    const int lrA = (lane & 7) + ((lane >> 3) & 1) * 8;
    const int kgA = (lane >> 4) * 8;
    const int lrB = (lane & 7) + ((lane >> 4) & 1) * 8;
    const int kgB = ((lane >> 3) & 1) * 8;

    uint32_t sA_u = (uint32_t)__cvta_generic_to_shared(sA);
    uint32_t sB_u = (uint32_t)__cvta_generic_to_shared(sB);

    float acc[2][8][4];
#pragma unroll
    for (int mi = 0; mi < 2; mi++)
#pragma unroll
        for (int ni = 0; ni < 8; ni++)
#pragma unroll
            for (int t = 0; t < 4; t++) acc[mi][ni][t] = 0.f;

    const int NK = FF / BK;  // 64

    auto load_stage = [&](int st, int k0) {
#pragma unroll
        for (int i = 0; i < 4; i++) {
            int idx = tid + i * 256;
            int row = idx >> 3, c16 = (idx & 7) * 8;
            cp16(sA_u + (st * STA_H + row * PITCH + c16) * 2,
                 g_h + (size_t)(r0 + row) * FF + k0 + c16);
        }
#pragma unroll
        for (int i = 0; i < 4; i++) {
            int idx = tid + i * 256;
            int row = idx >> 3, c16 = (idx & 7) * 8;
            cp16(sB_u + (st * STB_H + row * PITCH + c16) * 2,
                 W2 + (size_t)(n0 + row) * FF + k0 + c16);
        }
        CP_COMMIT();
    };

    load_stage(0, 0);

    for (int k = 0; k < NK; k++) {
        int st = k & 1;
        if (k + 1 < NK) {
            load_stage(st ^ 1, (k + 1) * BK);
            asm volatile("cp.async.wait_group 1;\n");
        } else {
            asm volatile("cp.async.wait_group 0;\n");
        }
        __syncthreads();

        uint32_t Au = sA_u + st * STA_H * 2;
        uint32_t Bu = sB_u + st * STB_H * 2;
#pragma unroll
        for (int c = 0; c < 4; c++) {
            int kc = c * 16;
            uint32_t a[2][4];
#pragma unroll
            for (int mi = 0; mi < 2; mi++)
                ldsm4(a[mi], Au + ((wm + mi * 16 + lrA) * PITCH + kc + kgA) * 2);
#pragma unroll
            for (int p = 0; p < 4; p++) {
                uint32_t b[4];
                ldsm4(b, Bu + ((wn + p * 16 + lrB) * PITCH + kc + kgB) * 2);
#pragma unroll
                for (int mi = 0; mi < 2; mi++) {
                    mma_f16(acc[mi][p * 2 + 0], a[mi], b[0], b[1]);
                    mma_f16(acc[mi][p * 2 + 1], a[mi], b[2], b[3]);
                }
            }
        }
        __syncthreads();
    }

    // Epilogue: plain stores to g_o
#pragma unroll
    for (int mi = 0; mi < 2; mi++) {
#pragma unroll
        for (int t2 = 0; t2 < 2; t2++) {
            int row = r0 + wm + mi * 16 + grp + t2 * 8;
            float* op = g_o + (size_t)row * DD + n0;
#pragma unroll
            for (int ni = 0; ni < 8; ni++) {
                float2 v = make_float2(acc[mi][ni][t2 * 2 + 0], acc[mi][ni][t2 * 2 + 1]);
                *reinterpret_cast<float2*>(op + wn + ni * 8 + qid * 2) = v;
            }
        }
    }
}

// ---------------------------------------------------------------------------
// Combine: out[t] = w0 * g_o[pos0] + w1 * g_o[pos1]
__global__ void combine_kernel(float* __restrict__ out) {
    const int NC4 = DD / 4;
    int idx = blockIdx.x * blockDim.x + threadIdx.x;
    int stride = gridDim.x * blockDim.x;
    for (int i = idx; i < NT * NC4; i += stride) {
        int t = i / NC4, c = i % NC4;
        int p0 = g_tpos[2 * t + 0], p1 = g_tpos[2 * t + 1];
        float w0 = g_wt[p0], w1 = g_wt[p1];
        float4 v0 = reinterpret_cast<const float4*>(g_o)[(size_t)p0 * NC4 + c];
        float4 v1 = reinterpret_cast<const float4*>(g_o)[(size_t)p1 * NC4 + c];
        float4 r;
        r.x = w0 * v0.x + w1 * v1.x;
        r.y = w0 * v0.y + w1 * v1.y;
        r.z = w0 * v0.z + w1 * v1.z;
        r.w = w0 * v0.w + w1 * v1.w;
        reinterpret_cast<float4*>(out)[i] = r;
    }
}

// ---------------------------------------------------------------------------
extern "C" void kernel_launch(void* const* d_in, const int* in_sizes, int n_in,
                              void* d_out, int out_size) {
    const float* x  = (const float*)d_in[0];
    const float* gw = (const float*)d_in[1];
    const float* w1 = (const float*)d_in[2];
    const float* w3 = (const float*)d_in[3];
    const float* w2 = (const float*)d_in[4];
    float* out = (float*)d_out;

    cudaFuncSetAttribute(ffn1_kernel, cudaFuncAttributeMaxDynamicSharedMemorySize, SMEM_BYTES);
    cudaFuncSetAttribute(ffn2_kernel, cudaFuncAttributeMaxDynamicSharedMemorySize, SMEM_BYTES);

    init_kernel<<<256, 256>>>();
    router_kernel<<<NT / 8, 256>>>(x, gw);
    offsets_kernel<<<1, 1>>>();
    scatter_kernel<<<(NT + 255) / 256, 256>>>();
    gather_half_kernel<<<4096, 256>>>(x);
    transpose_half_kernel<<<dim3(4096, 24), 256>>>(w1, w3, w2);
    ffn1_kernel<<<MTP * (FF / BN1), 256, SMEM_BYTES>>>();
    ffn2_kernel<<<MTP * (DD / BN2), 256, SMEM_BYTES>>>();
    combine_kernel<<<2048, 256>>>(out);
}

// round 9
// speedup vs baseline: 2.3966x; 1.0002x over previous
#include <cuda_runtime.h>
#include <cuda_fp16.h>
#include <cstdint>
#include <math.h>

#define NT 8192
#define DD 1024
#define FF 4096
#define NE 8
#define BM 128
#define BK 64
#define BN1 64
#define BN2 128
#define MAX_ROWS (NT*2 + NE*BM)   // 17408
#define MT (MAX_ROWS/BM)          // 136
#define GROUP 16
#define MTP (((MT+GROUP-1)/GROUP)*GROUP)   // 144

#define PITCH 72                     // halves per smem row (144B)
#define STA_H (BM*PITCH)             // 9216 halves
#define STB_H (128*PITCH)            // 9216 halves
#define STG_H (STA_H + STB_H)        // 18432 halves per stage
#define NSTAGE 3
#define SMEM_BYTES (NSTAGE * STG_H * 2)   // 110592

__device__ __align__(128) __half g_h[(size_t)MAX_ROWS * FF];
__device__ __align__(128) __half g_xh[(size_t)MAX_ROWS * DD];
__device__ __align__(128) __half g_w1t[(size_t)NE * FF * DD];
__device__ __align__(128) __half g_w3t[(size_t)NE * FF * DD];
__device__ __align__(128) __half g_w2t[(size_t)NE * DD * FF];
__device__ __align__(128) float  g_o[(size_t)MAX_ROWS * DD];
__device__ int   g_perm[MAX_ROWS];
__device__ float g_wt[MAX_ROWS];
__device__ int   g_tpos[NT * 2];
__device__ int   g_counts[NE];
__device__ int   g_offs[NE + 1];
__device__ int   g_cursor[NE];
__device__ int   g_eid[NT * 2];
__device__ float g_wr[NT * 2];

__device__ __forceinline__ void mma_f16(float c[4], const uint32_t a[4], const uint32_t b0, const uint32_t b1) {
    asm volatile(
        "mma.sync.aligned.m16n8k16.row.col.f32.f16.f16.f32 "
        "{%0,%1,%2,%3}, {%4,%5,%6,%7}, {%8,%9}, {%0,%1,%2,%3};\n"
        : "+f"(c[0]), "+f"(c[1]), "+f"(c[2]), "+f"(c[3])
        : "r"(a[0]), "r"(a[1]), "r"(a[2]), "r"(a[3]), "r"(b0), "r"(b1));
}
__device__ __forceinline__ void ldsm4(uint32_t r[4], uint32_t addr) {
    asm volatile("ldmatrix.sync.aligned.m8n8.x4.shared.b16 {%0,%1,%2,%3}, [%4];"
                 : "=r"(r[0]), "=r"(r[1]), "=r"(r[2]), "=r"(r[3]) : "r"(addr));
}
__device__ __forceinline__ void cp16(uint32_t dst, const void* src) {
    asm volatile("cp.async.cg.shared.global [%0], [%1], 16;\n" :: "r"(dst), "l"(src));
}
#define CP_COMMIT() asm volatile("cp.async.commit_group;\n")
#define CP_WAIT1()  asm volatile("cp.async.wait_group 1;\n")
#define CP_WAIT0()  asm volatile("cp.async.wait_group 0;\n")

// ---------------------------------------------------------------------------
__global__ void init_kernel() {
    int idx = blockIdx.x * blockDim.x + threadIdx.x;
    int stride = gridDim.x * blockDim.x;
    for (int i = idx; i < MAX_ROWS; i += stride) g_perm[i] = -1;
    if (idx < NE) g_counts[idx] = 0;
}

__global__ void router_kernel(const float* __restrict__ x, const float* __restrict__ gw) {
    int warp = (blockIdx.x * blockDim.x + threadIdx.x) >> 5;
    int lane = threadIdx.x & 31;
    if (warp >= NT) return;
    const float* xr = x + (size_t)warp * DD;
    float acc[NE];
#pragma unroll
    for (int e = 0; e < NE; e++) acc[e] = 0.f;
    for (int d = lane; d < DD; d += 32) {
        float xv = xr[d];
        const float* g = gw + d * NE;
#pragma unroll
        for (int e = 0; e < NE; e++) acc[e] += xv * g[e];
    }
#pragma unroll
    for (int e = 0; e < NE; e++)
#pragma unroll
        for (int o = 16; o > 0; o >>= 1)
            acc[e] += __shfl_xor_sync(0xFFFFFFFFu, acc[e], o);
    if (lane == 0) {
        int i0 = 0; float v0 = acc[0];
#pragma unroll
        for (int e = 1; e < NE; e++) if (acc[e] > v0) { v0 = acc[e]; i0 = e; }
        int i1 = -1; float v1 = -1e30f;
#pragma unroll
        for (int e = 0; e < NE; e++) {
            if (e == i0) continue;
            if (acc[e] > v1) { v1 = acc[e]; i1 = e; }
        }
        float e1 = expf(v1 - v0);
        float inv = 1.f / (1.f + e1);
        g_eid[2 * warp + 0] = i0; g_wr[2 * warp + 0] = inv;
        g_eid[2 * warp + 1] = i1; g_wr[2 * warp + 1] = e1 * inv;
        atomicAdd(&g_counts[i0], 1);
        atomicAdd(&g_counts[i1], 1);
    }
}

__global__ void offsets_kernel() {
    int acc = 0;
    for (int e = 0; e < NE; e++) {
        g_offs[e] = acc; g_cursor[e] = acc;
        acc += (g_counts[e] + BM - 1) / BM * BM;
    }
    g_offs[NE] = acc;
}

__global__ void scatter_kernel() {
    int t = blockIdx.x * blockDim.x + threadIdx.x;
    if (t >= NT) return;
#pragma unroll
    for (int k = 0; k < 2; k++) {
        int e = g_eid[2 * t + k];
        int pos = atomicAdd(&g_cursor[e], 1);
        g_perm[pos] = t;
        g_wt[pos] = g_wr[2 * t + k];
        g_tpos[2 * t + k] = pos;
    }
}

__global__ void gather_half_kernel(const float* __restrict__ x) {
    const int NC8 = DD / 8;
    int idx = blockIdx.x * blockDim.x + threadIdx.x;
    int stride = gridDim.x * blockDim.x;
    for (int i = idx; i < MAX_ROWS * NC8; i += stride) {
        int r = i / NC8, c8 = i % NC8;
        int p = g_perm[r];
        union { uint4 u; __half2 h[4]; } pk;
        if (p >= 0) {
            const float4* xs = reinterpret_cast<const float4*>(x + (size_t)p * DD + c8 * 8);
            float4 v0 = xs[0], v1 = xs[1];
            pk.h[0] = __floats2half2_rn(v0.x, v0.y);
            pk.h[1] = __floats2half2_rn(v0.z, v0.w);
            pk.h[2] = __floats2half2_rn(v1.x, v1.y);
            pk.h[3] = __floats2half2_rn(v1.z, v1.w);
        } else {
            pk.u = make_uint4(0, 0, 0, 0);
        }
        reinterpret_cast<uint4*>(g_xh)[(size_t)r * NC8 + c8] = pk.u;
    }
}

__global__ void transpose_half_kernel(const float* __restrict__ w1,
                                      const float* __restrict__ w3,
                                      const float* __restrict__ w2) {
    __shared__ float s[32][33];
    int z = blockIdx.y, m = z >> 3, e = z & 7;
    const float* src; __half* dst; int R, C;
    if (m == 0)      { src = w1 + (size_t)e * DD * FF; dst = g_w1t + (size_t)e * FF * DD; R = DD; C = FF; }
    else if (m == 1) { src = w3 + (size_t)e * DD * FF; dst = g_w3t + (size_t)e * FF * DD; R = DD; C = FF; }
    else             { src = w2 + (size_t)e * FF * DD; dst = g_w2t + (size_t)e * DD * FF; R = FF; C = DD; }
    int tpc = C / 32;
    int r0 = (blockIdx.x / tpc) * 32, c0 = (blockIdx.x % tpc) * 32;
    int rr = threadIdx.x >> 5, cc = threadIdx.x & 31;
#pragma unroll
    for (int i = 0; i < 4; i++)
        s[rr + 8 * i][cc] = src[(size_t)(r0 + rr + 8 * i) * C + c0 + cc];
    __syncthreads();
#pragma unroll
    for (int i = 0; i < 4; i++)
        dst[(size_t)(c0 + rr + 8 * i) * R + r0 + cc] = __float2half_rn(s[cc][rr + 8 * i]);
}

// ---------------------------------------------------------------------------
// FFN1: h = silu(X W1) * (X W3). 3-stage cp.async pipeline, 1 barrier/iter.
__global__ __launch_bounds__(256, 2) void ffn1_kernel() {
    extern __shared__ __half smem_h[];

    const int NBT = FF / BN1;  // 64
    int bid = blockIdx.x;
    int tm = (bid / (GROUP * NBT)) * GROUP + (bid % GROUP);
    int nb = (bid % (GROUP * NBT)) / GROUP;
    if (tm >= MT) return;
    const int r0 = tm * BM;
    if (r0 >= g_offs[NE]) return;
    const int n0 = nb * BN1;

    int e = NE - 1;
#pragma unroll
    for (int i = 0; i < NE; i++)
        if (r0 >= g_offs[i] && r0 < g_offs[i + 1]) e = i;
    const __half* W1 = g_w1t + (size_t)e * FF * DD;
    const __half* W3 = g_w3t + (size_t)e * FF * DD;

    const int tid = threadIdx.x;
    const int lane = tid & 31, warp = tid >> 5;
    const int wm = (warp >> 1) * 32, wn = (warp & 1) * 32;
    const int grp = lane >> 2, qid = lane & 3;

    const int lrA = (lane & 7) + ((lane >> 3) & 1) * 8;
    const int kgA = (lane >> 4) * 8;
    const int lrB = (lane & 7) + ((lane >> 4) & 1) * 8;
    const int kgB = ((lane >> 3) & 1) * 8;

    uint32_t sm_u = (uint32_t)__cvta_generic_to_shared(smem_h);

    float acc1[2][4][4], acc3[2][4][4];
#pragma unroll
    for (int mi = 0; mi < 2; mi++)
#pragma unroll
        for (int ni = 0; ni < 4; ni++)
#pragma unroll
            for (int t = 0; t < 4; t++) { acc1[mi][ni][t] = 0.f; acc3[mi][ni][t] = 0.f; }

    const int NK = DD / BK;  // 16

    auto load_stage = [&](int slot, int k0) {
        uint32_t base = sm_u + slot * STG_H * 2;
#pragma unroll
        for (int i = 0; i < 4; i++) {
            int idx = tid + i * 256;
            int row = idx >> 3, c16 = (idx & 7) * 8;
            cp16(base + (row * PITCH + c16) * 2,
                 g_xh + (size_t)(r0 + row) * DD + k0 + c16);
        }
#pragma unroll
        for (int i = 0; i < 4; i++) {
            int idx = tid + i * 256;
            int mat = idx >> 9, row = (idx >> 3) & 63, c16 = (idx & 7) * 8;
            const __half* W = mat ? W3 : W1;
            cp16(base + (STA_H + (mat * 64 + row) * PITCH + c16) * 2,
                 W + (size_t)(n0 + row) * DD + k0 + c16);
        }
        CP_COMMIT();
    };

    load_stage(0, 0);
    load_stage(1, BK);

    for (int k = 0; k < NK; k++) {
        if (k + 1 < NK) CP_WAIT1(); else CP_WAIT0();
        __syncthreads();
        if (k + 2 < NK) load_stage((k + 2) % NSTAGE, (k + 2) * BK);

        int slot = k % NSTAGE;
        uint32_t Au = sm_u + slot * STG_H * 2;
        uint32_t Bu = Au + STA_H * 2;
#pragma unroll
        for (int c = 0; c < 4; c++) {
            int kc = c * 16;
            uint32_t a[2][4];
#pragma unroll
            for (int mi = 0; mi < 2; mi++)
                ldsm4(a[mi], Au + ((wm + mi * 16 + lrA) * PITCH + kc + kgA) * 2);
#pragma unroll
            for (int mat = 0; mat < 2; mat++) {
#pragma unroll
                for (int p = 0; p < 2; p++) {
                    uint32_t b[4];
                    ldsm4(b, Bu + ((mat * 64 + wn + p * 16 + lrB) * PITCH + kc + kgB) * 2);
#pragma unroll
                    for (int mi = 0; mi < 2; mi++) {
                        float* d0 = mat ? acc3[mi][p * 2 + 0] : acc1[mi][p * 2 + 0];
                        float* d1 = mat ? acc3[mi][p * 2 + 1] : acc1[mi][p * 2 + 1];
                        mma_f16(d0, a[mi], b[0], b[1]);
                        mma_f16(d1, a[mi], b[2], b[3]);
                    }
                }
            }
        }
    }

#pragma unroll
    for (int mi = 0; mi < 2; mi++)
#pragma unroll
        for (int ni = 0; ni < 4; ni++)
#pragma unroll
            for (int t2 = 0; t2 < 2; t2++) {
                int row = r0 + wm + mi * 16 + grp + t2 * 8;
                int col = n0 + wn + ni * 8 + qid * 2;
                float a0 = acc1[mi][ni][t2 * 2 + 0], a1 = acc1[mi][ni][t2 * 2 + 1];
                float s0 = a0 / (1.f + expf(-a0)) * acc3[mi][ni][t2 * 2 + 0];
                float s1 = a1 / (1.f + expf(-a1)) * acc3[mi][ni][t2 * 2 + 1];
                *reinterpret_cast<__half2*>(g_h + (size_t)row * FF + col) =
                    __floats2half2_rn(s0, s1);
            }
}

// ---------------------------------------------------------------------------
// FFN2: g_o[row] = h[row] @ W2. 3-stage pipeline, 1 barrier/iter.
__global__ __launch_bounds__(256, 2) void ffn2_kernel() {
    extern __shared__ __half smem_h[];

    const int NBT = DD / BN2;  // 8
    int bid = blockIdx.x;
    int tm = (bid / (GROUP * NBT)) * GROUP + (bid % GROUP);
    int nb = (bid % (GROUP * NBT)) / GROUP;
    if (tm >= MT) return;
    const int r0 = tm * BM;
    if (r0 >= g_offs[NE]) return;
    const int n0 = nb * BN2;

    int e = NE - 1;
#pragma unroll
    for (int i = 0; i < NE; i++)
        if (r0 >= g_offs[i] && r0 < g_offs[i + 1]) e = i;
    const __half* W2 = g_w2t + (size_t)e * DD * FF;

    const int tid = threadIdx.x;
    const int lane = tid & 31, warp = tid >> 5;
    const int wm = (warp >> 1) * 32, wn = (warp & 1) * 64;
    const int grp = lane >> 2, qid = lane & 3;

    const int lrA = (lane & 7) + ((lane >> 3) & 1) * 8;
    const int kgA = (lane >> 4) * 8;
    const int lrB = (lane & 7) + ((lane >> 4) & 1) * 8;
    const int kgB = ((lane >> 3) & 1) * 8;

    uint32_t sm_u = (uint32_t)__cvta_generic_to_shared(smem_h);

    float acc[2][8][4];
#pragma unroll
    for (int mi = 0; mi < 2; mi++)
#pragma unroll
        for (int ni = 0; ni < 8; ni++)
#pragma unroll
            for (int t = 0; t < 4; t++) acc[mi][ni][t] = 0.f;

    const int NK = FF / BK;  // 64

    auto load_stage = [&](int slot, int k0) {
        uint32_t base = sm_u + slot * STG_H * 2;
#pragma unroll
        for (int i = 0; i < 4; i++) {
            int idx = tid + i * 256;
            int row = idx >> 3, c16 = (idx & 7) * 8;
            cp16(base + (row * PITCH + c16) * 2,
                 g_h + (size_t)(r0 + row) * FF + k0 + c16);
        }
#pragma unroll
        for (int i = 0; i < 4; i++) {
            int idx = tid + i * 256;
            int row = idx >> 3, c16 = (idx & 7) * 8;
            cp16(base + (STA_H + row * PITCH + c16) * 2,
                 W2 + (size_t)(n0 + row) * FF + k0 + c16);
        }
        CP_COMMIT();
    };

    load_stage(0, 0);
    load_stage(1, BK);

    for (int k = 0; k < NK; k++) {
        if (k + 1 < NK) CP_WAIT1(); else CP_WAIT0();
        __syncthreads();
        if (k + 2 < NK) load_stage((k + 2) % NSTAGE, (k + 2) * BK);

        int slot = k % NSTAGE;
        uint32_t Au = sm_u + slot * STG_H * 2;
        uint32_t Bu = Au + STA_H * 2;
#pragma unroll
        for (int c = 0; c < 4; c++) {
            int kc = c * 16;
            uint32_t a[2][4];
#pragma unroll
            for (int mi = 0; mi < 2; mi++)
                ldsm4(a[mi], Au + ((wm + mi * 16 + lrA) * PITCH + kc + kgA) * 2);
#pragma unroll
            for (int p = 0; p < 4; p++) {
                uint32_t b[4];
                ldsm4(b, Bu + ((wn + p * 16 + lrB) * PITCH + kc + kgB) * 2);
#pragma unroll
                for (int mi = 0; mi < 2; mi++) {
                    mma_f16(acc[mi][p * 2 + 0], a[mi], b[0], b[1]);
                    mma_f16(acc[mi][p * 2 + 1], a[mi], b[2], b[3]);
                }
            }
        }
    }

#pragma unroll
    for (int mi = 0; mi < 2; mi++) {
#pragma unroll
        for (int t2 = 0; t2 < 2; t2++) {
            int row = r0 + wm + mi * 16 + grp + t2 * 8;
            float* op = g_o + (size_t)row * DD + n0;
#pragma unroll
            for (int ni = 0; ni < 8; ni++) {
                float2 v = make_float2(acc[mi][ni][t2 * 2 + 0], acc[mi][ni][t2 * 2 + 1]);
                *reinterpret_cast<float2*>(op + wn + ni * 8 + qid * 2) = v;
            }
        }
    }
}

// ---------------------------------------------------------------------------
__global__ void combine_kernel(float* __restrict__ out) {
    const int NC4 = DD / 4;
    int idx = blockIdx.x * blockDim.x + threadIdx.x;
    int stride = gridDim.x * blockDim.x;
    for (int i = idx; i < NT * NC4; i += stride) {
        int t = i / NC4, c = i % NC4;
        int p0 = g_tpos[2 * t + 0], p1 = g_tpos[2 * t + 1];
        float w0 = g_wt[p0], w1 = g_wt[p1];
        float4 v0 = reinterpret_cast<const float4*>(g_o)[(size_t)p0 * NC4 + c];
        float4 v1 = reinterpret_cast<const float4*>(g_o)[(size_t)p1 * NC4 + c];
        float4 r;
        r.x = w0 * v0.x + w1 * v1.x;
        r.y = w0 * v0.y + w1 * v1.y;
        r.z = w0 * v0.z + w1 * v1.z;
        r.w = w0 * v0.w + w1 * v1.w;
        reinterpret_cast<float4*>(out)[i] = r;
    }
}

// ---------------------------------------------------------------------------
extern "C" void kernel_launch(void* const* d_in, const int* in_sizes, int n_in,
                              void* d_out, int out_size) {
    const float* x  = (const float*)d_in[0];
    const float* gw = (const float*)d_in[1];
    const float* w1 = (const float*)d_in[2];
    const float* w3 = (const float*)d_in[3];
    const float* w2 = (const float*)d_in[4];
    float* out = (float*)d_out;

    cudaFuncSetAttribute(ffn1_kernel, cudaFuncAttributeMaxDynamicSharedMemorySize, SMEM_BYTES);
    cudaFuncSetAttribute(ffn2_kernel, cudaFuncAttributeMaxDynamicSharedMemorySize, SMEM_BYTES);

    init_kernel<<<256, 256>>>();
    router_kernel<<<NT / 8, 256>>>(x, gw);
    offsets_kernel<<<1, 1>>>();
    scatter_kernel<<<(NT + 255) / 256, 256>>>();
    gather_half_kernel<<<4096, 256>>>(x);
    transpose_half_kernel<<<dim3(4096, 24), 256>>>(w1, w3, w2);
    ffn1_kernel<<<MTP * (FF / BN1), 256, SMEM_BYTES>>>();
    ffn2_kernel<<<MTP * (DD / BN2), 256, SMEM_BYTES>>>();
    combine_kernel<<<2048, 256>>>(out);
}